// round 3
// baseline (speedup 1.0000x reference)
#include <cuda_runtime.h>
#include <math_constants.h>

// out[n] = h( max_l min_f max_c |A[n,l,c] - B[c,f]| ),  h(D) = t/(1+t)^2, t = exp(-10 D)
// Identity: sigmoid(10x)*sigmoid(-10x) = h(|x|), h strictly decreasing => all
// reductions (min over channel-g, max over f, min over l) commute through h.

#define NB 64
#define LB 512
#define FB 2048
#define THREADS 256
#define F_PER (FB / 4)   // 512 f per thread (4 f-quarters per block)

__device__ unsigned int g_dmax[NB];   // float bits of per-n running max (nonneg)

__global__ void psl_init_kernel() {
    int i = threadIdx.x;
    if (i < NB) g_dmax[i] = 0u;   // d >= 0, so 0 is identity for max
}

__global__ __launch_bounds__(THREADS)
void psl_main_kernel(const float* __restrict__ A, const float* __restrict__ B) {
    __shared__ float2 sB[FB];        // interleaved (B0[f], B1[f]) pairs, 16 KB
    __shared__ float sRed[THREADS];

    const int n      = blockIdx.x;   // 0..63
    const int lchunk = blockIdx.y;   // 0..7, 64 l's each
    const int tid    = threadIdx.x;

    // Stage B into shared memory, interleaved so one LDS.64 fetches both channels.
    for (int i = tid; i < FB; i += THREADS) {
        sB[i] = make_float2(B[i], B[FB + i]);
    }
    __syncthreads();

    // tid layout: fq = tid>>6 (warp-uniform -> broadcast LDS), li = tid&63
    const int fq = tid >> 6;         // f-quarter 0..3
    const int li = tid & 63;
    const int l  = lchunk * 64 + li;

    const float* a = A + ((size_t)n * LB + l) * 2;
    const float a0 = a[0];
    const float a1 = a[1];

    const float2* p = sB + fq * F_PER;

    // 4 independent min accumulators to break the FMNMX dependency chain.
    float m0 = CUDART_INF_F, m1 = CUDART_INF_F, m2 = CUDART_INF_F, m3 = CUDART_INF_F;

    #pragma unroll 8
    for (int j = 0; j < F_PER; j += 4) {
        float2 b0 = p[j + 0];
        float2 b1 = p[j + 1];
        float2 b2 = p[j + 2];
        float2 b3 = p[j + 3];
        m0 = fminf(m0, fmaxf(fabsf(a0 - b0.x), fabsf(a1 - b0.y)));
        m1 = fminf(m1, fmaxf(fabsf(a0 - b1.x), fabsf(a1 - b1.y)));
        m2 = fminf(m2, fmaxf(fabsf(a0 - b2.x), fabsf(a1 - b2.y)));
        m3 = fminf(m3, fmaxf(fabsf(a0 - b3.x), fabsf(a1 - b3.y)));
    }
    float m = fminf(fminf(m0, m1), fminf(m2, m3));

    sRed[tid] = m;
    __syncthreads();

    // Combine the 4 f-quarters per l (min), then block max over the 64 l's.
    if (tid < 64) {
        float v = fminf(fminf(sRed[tid], sRed[tid + 64]),
                        fminf(sRed[tid + 128], sRed[tid + 192]));
        #pragma unroll
        for (int off = 16; off; off >>= 1)
            v = fmaxf(v, __shfl_xor_sync(0xffffffffu, v, off));
        if ((tid & 31) == 0) sRed[tid >> 5] = v;  // writes to [0],[1]; readers use >=32 or own lane
    }
    __syncthreads();

    if (tid == 0) {
        float v = fmaxf(sRed[0], sRed[1]);
        // Nonnegative floats: uint bit-pattern compare == float compare.
        atomicMax(&g_dmax[n], __float_as_uint(v));
    }
}

__global__ void psl_finalize_kernel(float* __restrict__ out) {
    int n = threadIdx.x;
    if (n < NB) {
        float D = __uint_as_float(g_dmax[n]);
        // h(D) = sigmoid(10D)*sigmoid(-10D) = t/(1+t)^2, t = exp(-10D), D>=0 so t<=1.
        float t = expf(-10.0f * D);
        float u = 1.0f + t;
        out[n] = t / (u * u);
    }
}

extern "C" void kernel_launch(void* const* d_in, const int* in_sizes, int n_in,
                              void* d_out, int out_size) {
    const float* A = (const float*)d_in[0];
    const float* B = (const float*)d_in[1];
    // Defensive: identify by element count (A = 64*512*2 = 65536, B = 2*2048 = 4096).
    if (n_in >= 2 && in_sizes[0] == 4096 && in_sizes[1] == 65536) {
        const float* tmp = A; A = B; B = tmp;
    }
    float* out = (float*)d_out;

    psl_init_kernel<<<1, 64>>>();
    dim3 grid(NB, LB / 64);   // 64 x 8 = 512 blocks
    psl_main_kernel<<<grid, THREADS>>>(A, B);
    psl_finalize_kernel<<<1, 64>>>(out);
}

// round 4
// speedup vs baseline: 1.2448x; 1.2448x over previous
#include <cuda_runtime.h>
#include <math_constants.h>

// out[n] = h( max_l min_f max_c |A[n,l,c] - B[c,f]| ),  h(D) = t/(1+t)^2, t = exp(-10 D)
// Identity: sigmoid(10x)*sigmoid(-10x) = h(|x|); h strictly decreasing => all
// reductions (min over channel-g, max over f, min over l) commute through h.
//
// Single fused kernel: per-n arrival counters + last-block-finalizes. All
// __device__ state returns to zero at the end of every launch (graph-replay safe).

#define NB 64
#define LB 512
#define FB 2048
#define THREADS 256
#define LCHUNKS 16
#define L_PER 32                 // l's per block
#define FQ_COUNT 8               // f-octants per block (tid>>5)
#define F_PER (FB / FQ_COUNT)    // 256 f per thread

__device__ unsigned int g_dmax[NB];    // float bits of per-n running max (nonneg); 0 at rest
__device__ unsigned int g_count[NB];   // arrival counters; 0 at rest

__device__ __forceinline__ unsigned long long pack2(float x, float y) {
    unsigned long long r;
    asm("mov.b64 %0, {%1, %2};" : "=l"(r) : "f"(x), "f"(y));
    return r;
}

// Packed fp32x2 add (Blackwell): one fma-pipe instruction for both channels.
__device__ __forceinline__ float2 addf32x2(unsigned long long a, unsigned long long b) {
    unsigned long long d;
    asm("add.rn.f32x2 %0, %1, %2;" : "=l"(d) : "l"(a), "l"(b));
    float lo, hi;
    asm("mov.b64 {%0, %1}, %2;" : "=f"(lo), "=f"(hi) : "l"(d));
    return make_float2(lo, hi);
}

__global__ __launch_bounds__(THREADS)
void psl_fused_kernel(const float* __restrict__ A, const float* __restrict__ B,
                      float* __restrict__ out) {
    __shared__ __align__(16) float2 sB[FB];   // NEGATED, interleaved (-B0[f], -B1[f]); 16 KB
    __shared__ float sRed[THREADS];

    const int n      = blockIdx.x;   // 0..63
    const int lchunk = blockIdx.y;   // 0..15
    const int tid    = threadIdx.x;

    // Stage negated B so packed add computes (a - b).
    for (int i = tid; i < FB; i += THREADS) {
        sB[i] = make_float2(-B[i], -B[FB + i]);
    }
    __syncthreads();

    // tid layout: fq = tid>>5 (warp-uniform -> pure smem broadcast), li = tid&31
    const int fq = tid >> 5;         // f-octant 0..7
    const int li = tid & 31;
    const int l  = lchunk * L_PER + li;

    const float* a = A + ((size_t)n * LB + l) * 2;
    const unsigned long long ap = pack2(a[0], a[1]);

    // 16-byte smem reads: each ulonglong2 holds two f's worth of (b0,b1) pairs.
    const ulonglong2* p = reinterpret_cast<const ulonglong2*>(sB + fq * F_PER);

    float m0 = CUDART_INF_F, m1 = CUDART_INF_F, m2 = CUDART_INF_F, m3 = CUDART_INF_F;

    #pragma unroll 8
    for (int j = 0; j < F_PER / 2; j += 2) {   // 4 f per iteration
        ulonglong2 q0 = p[j];
        ulonglong2 q1 = p[j + 1];
        float2 d0 = addf32x2(ap, q0.x);
        float2 d1 = addf32x2(ap, q0.y);
        float2 d2 = addf32x2(ap, q1.x);
        float2 d3 = addf32x2(ap, q1.y);
        m0 = fminf(m0, fmaxf(fabsf(d0.x), fabsf(d0.y)));
        m1 = fminf(m1, fmaxf(fabsf(d1.x), fabsf(d1.y)));
        m2 = fminf(m2, fmaxf(fabsf(d2.x), fabsf(d2.y)));
        m3 = fminf(m3, fmaxf(fabsf(d3.x), fabsf(d3.y)));
    }
    float m = fminf(fminf(m0, m1), fminf(m2, m3));

    sRed[tid] = m;
    __syncthreads();

    if (tid < 32) {
        // Combine the 8 f-octants per l (min), then max over the 32 l's.
        float v = sRed[tid];
        #pragma unroll
        for (int k = 32; k < THREADS; k += 32) v = fminf(v, sRed[tid + k]);
        #pragma unroll
        for (int off = 16; off; off >>= 1)
            v = fmaxf(v, __shfl_xor_sync(0xffffffffu, v, off));

        if (tid == 0) {
            // Nonnegative floats: uint bit-pattern compare == float compare.
            atomicMax(&g_dmax[n], __float_as_uint(v));
            __threadfence();   // release: publish max before signaling arrival
            unsigned int old = atomicAdd(&g_count[n], 1u);
            if (old == LCHUNKS - 1) {
                __threadfence();
                // Read-and-reset in one atomic; state returns to 0 for next replay.
                unsigned int dbits = atomicExch(&g_dmax[n], 0u);
                atomicExch(&g_count[n], 0u);
                float D = __uint_as_float(dbits);
                // h(D) = sigmoid(10D)*sigmoid(-10D) = t/(1+t)^2, t = exp(-10D) <= 1.
                float t = expf(-10.0f * D);
                float u = 1.0f + t;
                out[n] = t / (u * u);
            }
        }
    }
}

extern "C" void kernel_launch(void* const* d_in, const int* in_sizes, int n_in,
                              void* d_out, int out_size) {
    const float* A = (const float*)d_in[0];
    const float* B = (const float*)d_in[1];
    // Defensive: identify by element count (A = 64*512*2 = 65536, B = 2*2048 = 4096).
    if (n_in >= 2 && in_sizes[0] == 4096 && in_sizes[1] == 65536) {
        const float* tmp = A; A = B; B = tmp;
    }
    float* out = (float*)d_out;

    dim3 grid(NB, LCHUNKS);   // 64 x 16 = 1024 blocks, ~6.9/SM, single wave
    psl_fused_kernel<<<grid, THREADS>>>(A, B, out);
}